// round 4
// baseline (speedup 1.0000x reference)
#include <cuda_runtime.h>

#define BG   16384
#define NN   14
#define FIN  128
#define HH   4
#define CC   64
#define HC   256       // H*C
#define EE   182
#define ET   196       // EE + NN self loops
#define LIN  896       // N*C
#define LOUT 32

// global scratch for h2 between kernels (static device array: allowed)
__device__ float g_h2[(size_t)BG * LIN];

// ---- kernel A shared-memory layout (float offsets) ----
#define OFF_W1   0        // 32768
#define OFF_W2   32768    // 16384
#define OFF_H    49152    // 3584  (14 x 256)
#define OFF_X    52736    // 1792  (14 x 128; reused as 14 x 64 for layer2 input)
#define OFF_A1S  54528    // 256
#define OFF_A1D  54784    // 256
#define OFF_A2S  55040    // 256
#define OFF_A2D  55296    // 256
#define OFF_B1   55552    // 64
#define OFF_B2   55616    // 64
#define OFF_AL   55680    // 112  ( [n][h][src/dst] )
#define OFF_DEN  55792    // 56   ( [d][h] )
#define OFF_AMAT 55848    // 784  ( [h][d][s] )
#define OFF_EDGE 56632    // 196 ints (s | d<<8)
#define OFF_FLAG 56828    // 1 int (edge dtype flag)
#define SMEM_A_FLOATS 56832
#define SMEM_A_BYTES  (SMEM_A_FLOATS * 4)

// ---------------------------------------------------------------------------
// small node-feature GEMM: sH[n][j] = sum_k sX[n][k] * sW[k][j], j = tid (256 cols)
// ---------------------------------------------------------------------------
template <int K>
__device__ __forceinline__ void node_gemm(const float* __restrict__ sX,
                                          const float* __restrict__ sW,
                                          float* __restrict__ sH, int tid)
{
    float acc[NN];
#pragma unroll
    for (int n = 0; n < NN; n++) acc[n] = 0.f;

#pragma unroll 2
    for (int k = 0; k < K; k += 4) {
        float w0 = sW[(k + 0) * HC + tid];
        float w1 = sW[(k + 1) * HC + tid];
        float w2 = sW[(k + 2) * HC + tid];
        float w3 = sW[(k + 3) * HC + tid];
#pragma unroll
        for (int n = 0; n < NN; n++) {
            float4 x4 = *(const float4*)(sX + n * K + k);
            acc[n] = fmaf(x4.x, w0, acc[n]);
            acc[n] = fmaf(x4.y, w1, acc[n]);
            acc[n] = fmaf(x4.z, w2, acc[n]);
            acc[n] = fmaf(x4.w, w3, acc[n]);
        }
    }
#pragma unroll
    for (int n = 0; n < NN; n++) sH[n * HC + tid] = acc[n];
}

// ---------------------------------------------------------------------------
// attention + aggregation over sh (in place). Caller: sh just written (no sync yet).
// ---------------------------------------------------------------------------
__device__ __forceinline__ void attention_layer(float* __restrict__ sm,
                                                const float* __restrict__ sas,
                                                const float* __restrict__ sad,
                                                int tid)
{
    float* sh   = sm + OFF_H;
    float* sAl  = sm + OFF_AL;
    float* sDen = sm + OFF_DEN;
    float* sA   = sm + OFF_AMAT;
    const int* sEdge = (const int*)(sm + OFF_EDGE);

    // zero scratch (previous consumers of these arrays are at least 2 syncs back)
    if (tid < 112) sAl[tid] = 0.f;
    if (tid >= 112 && tid < 112 + NN * HH) sDen[tid - 112] = 0.f;
    for (int i = tid; i < HH * NN * NN; i += 256) sA[i] = 0.f;
    __syncthreads();   // sh + zeros visible

    // attention logits: al[n][h] partial sums over 16-c chunks (224 threads)
    if (tid < 224) {
        int n = tid >> 4, h = (tid >> 2) & 3, q = tid & 3;
        const float* hp = sh + n * HC + h * CC + q * 16;
        const float* ap = sas + h * CC + q * 16;
        const float* bp = sad + h * CC + q * 16;
        float ss = 0.f, dd = 0.f;
#pragma unroll
        for (int c = 0; c < 16; c++) {
            float v = hp[c];
            ss = fmaf(v, ap[c], ss);
            dd = fmaf(v, bp[c], dd);
        }
        atomicAdd(&sAl[n * 8 + h * 2 + 0], ss);
        atomicAdd(&sAl[n * 8 + h * 2 + 1], dd);
    }
    __syncthreads();

    // pass 1: softmax denominators per (dst, h)
    if (tid < ET) {
        int e = sEdge[tid];
        int s = e & 255, d = (e >> 8) & 255;
#pragma unroll
        for (int h = 0; h < HH; h++) {
            float ev = sAl[s * 8 + h * 2 + 0] + sAl[d * 8 + h * 2 + 1];
            ev = (ev > 0.f) ? ev : 0.2f * ev;   // leaky relu
            atomicAdd(&sDen[d * 4 + h], expf(ev));
        }
    }
    __syncthreads();

    // pass 2: dense attention matrix A[h][d][s] += alpha
    if (tid < ET) {
        int e = sEdge[tid];
        int s = e & 255, d = (e >> 8) & 255;
#pragma unroll
        for (int h = 0; h < HH; h++) {
            float ev = sAl[s * 8 + h * 2 + 0] + sAl[d * 8 + h * 2 + 1];
            ev = (ev > 0.f) ? ev : 0.2f * ev;
            float alpha = expf(ev) / sDen[d * 4 + h];
            atomicAdd(&sA[(h * NN + d) * NN + s], alpha);
        }
    }
    __syncthreads();

    // aggregation: out[n][j] = sum_s A[h(j)][n][s] * sh[s][j]
    {
        int hj = tid >> 6;
        const float* Ab = sA + hj * NN * NN;
        float acc2[NN];
#pragma unroll
        for (int n = 0; n < NN; n++) acc2[n] = 0.f;
#pragma unroll
        for (int s = 0; s < NN; s++) {
            float hs = sh[s * HC + tid];
#pragma unroll
            for (int n = 0; n < NN; n++) acc2[n] = fmaf(Ab[n * NN + s], hs, acc2[n]);
        }
        __syncthreads();   // all reads of sh complete before overwrite
#pragma unroll
        for (int n = 0; n < NN; n++) sh[n * HC + tid] = acc2[n];
    }
    __syncthreads();
}

// ---------------------------------------------------------------------------
// kernel A: fused 2-layer GAT, writes h2 to g_h2
// ---------------------------------------------------------------------------
__global__ __launch_bounds__(256, 1)
void gat_fused_kernel(const float* __restrict__ feature,
                      const int* __restrict__ edge_raw,   // int32 OR int64 (detected)
                      const float* __restrict__ W1, const float* __restrict__ a_s1,
                      const float* __restrict__ a_d1, const float* __restrict__ b1,
                      const float* __restrict__ W2, const float* __restrict__ a_s2,
                      const float* __restrict__ a_d2, const float* __restrict__ b2)
{
    extern __shared__ float sm[];
    float* sW1  = sm + OFF_W1;
    float* sW2  = sm + OFF_W2;
    float* sh   = sm + OFF_H;
    float* sx   = sm + OFF_X;
    float* sa1s = sm + OFF_A1S;
    float* sa1d = sm + OFF_A1D;
    float* sa2s = sm + OFF_A2S;
    float* sa2d = sm + OFF_A2D;
    float* sb1  = sm + OFF_B1;
    float* sb2  = sm + OFF_B2;
    int*   sEdge = (int*)(sm + OFF_EDGE);
    int*   sFlag = (int*)(sm + OFF_FLAG);

    const int tid = threadIdx.x;

    // detect edge dtype: node ids are < 14, so for true int64 data every high
    // 32-bit word is 0; for int32 data these words are uniform values in [0,14)
    // (P(all 64 zero) = (1/14)^64 ~ 0). Deterministic for fixed inputs.
    if (tid == 0) {
        int allz = 1;
        for (int i = 0; i < 64; i++) allz &= (edge_raw[2 * i + 1] == 0);
        *sFlag = allz;   // 1 => int64, 0 => int32
    }

    // preload weights once per CTA
    {
        const float4* w1v = (const float4*)W1;
        float4* d1 = (float4*)sW1;
        for (int i = tid; i < FIN * HC / 4; i += 256) d1[i] = w1v[i];
        const float4* w2v = (const float4*)W2;
        float4* d2 = (float4*)sW2;
        for (int i = tid; i < CC * HC / 4; i += 256) d2[i] = w2v[i];
        sa1s[tid] = a_s1[tid];
        sa1d[tid] = a_d1[tid];
        sa2s[tid] = a_s2[tid];
        sa2d[tid] = a_d2[tid];
        if (tid < CC) { sb1[tid] = b1[tid]; sb2[tid] = b2[tid]; }
    }
    __syncthreads();
    const int is64 = *sFlag;

    for (int g = blockIdx.x; g < BG; g += gridDim.x) {
        // load node features + edges for this graph
        {
            const float4* xv = (const float4*)(feature + (size_t)g * (NN * FIN));
            float4* dx = (float4*)sx;
            for (int i = tid; i < NN * FIN / 4; i += 256) dx[i] = xv[i];
            if (tid < EE) {
                int s, d;
                if (is64) {
                    const long long* ep = (const long long*)edge_raw
                                          + ((size_t)g * EE + tid) * 2;
                    s = (int)ep[0];
                    d = (int)ep[1];
                } else {
                    const int* ep = edge_raw + ((size_t)g * EE + tid) * 2;
                    s = ep[0];
                    d = ep[1];
                }
                sEdge[tid] = s | (d << 8);
            } else if (tid < ET) {
                int v = tid - EE;
                sEdge[tid] = v | (v << 8);
            }
        }
        __syncthreads();

        // ---- layer 1 ----
        node_gemm<FIN>(sx, sW1, sh, tid);          // sh = x @ W1
        attention_layer(sm, sa1s, sa1d, tid);      // sh = aggregated [14][4*64]

        // mean over heads + bias + relu -> sx (reused as [14][64] layer-2 input)
        for (int i = tid; i < LIN; i += 256) {
            int n = i >> 6, c = i & 63;
            float m = 0.25f * (sh[n * HC + c] + sh[n * HC + CC + c] +
                               sh[n * HC + 2 * CC + c] + sh[n * HC + 3 * CC + c]) + sb1[c];
            sx[i] = fmaxf(m, 0.f);                 // i == n*64 + c
        }
        __syncthreads();

        // ---- layer 2 ----
        node_gemm<CC>(sx, sW2, sh, tid);           // sh = h1 @ W2
        attention_layer(sm, sa2s, sa2d, tid);

        // mean over heads + bias -> global scratch
        for (int i = tid; i < LIN; i += 256) {
            int n = i >> 6, c = i & 63;
            float m = 0.25f * (sh[n * HC + c] + sh[n * HC + CC + c] +
                               sh[n * HC + 2 * CC + c] + sh[n * HC + 3 * CC + c]) + sb2[c];
            g_h2[(size_t)g * LIN + i] = m;
        }
        // no sync needed: next-iter writes (sx/sEdge) don't alias sh/b2 reads here,
        // and GEMM1's sh writes are behind the post-load __syncthreads.
    }
}

// ---------------------------------------------------------------------------
// kernel B: z = h2 @ W_lin + b_lin ; p = z @ W_pred + b_pred ; out = sigmoid(p)
// one warp per graph; W_lin transposed (padded to 900) in smem.
// ---------------------------------------------------------------------------
#define WLT_PITCH 900
#define MLP_SMEM_FLOATS (LOUT * WLT_PITCH + 8 * LIN + 64)
#define MLP_SMEM_BYTES  (MLP_SMEM_FLOATS * 4)

__global__ __launch_bounds__(256, 1)
void gat_mlp_kernel(const float* __restrict__ Wlin, const float* __restrict__ blin,
                    const float* __restrict__ Wpred, const float* __restrict__ bpred,
                    float* __restrict__ out)
{
    extern __shared__ float sm[];
    float* sWt  = sm;                          // [32][900]
    float* sbuf = sm + LOUT * WLT_PITCH;       // [8][896]
    float* sb   = sbuf + 8 * LIN;              // [32]
    float* swp  = sb + LOUT;                   // [32]

    const int tid = threadIdx.x;
    const int lane = tid & 31;
    const int w = tid >> 5;

    // load W_lin transposed into smem
    for (int i = tid; i < LIN * LOUT; i += 256) {
        int r = i / LOUT, c = i - r * LOUT;    // Wlin[r][c]
        sWt[c * WLT_PITCH + r] = Wlin[i];
    }
    if (tid < LOUT) { sb[tid] = blin[tid]; swp[tid] = Wpred[tid]; }
    __syncthreads();
    const float bp = bpred[0];

    for (int g = blockIdx.x * 8 + w; g < BG; g += gridDim.x * 8) {
        const float* hrow = g_h2 + (size_t)g * LIN;
        float* buf = sbuf + w * LIN;
        for (int i = lane; i < LIN; i += 32) buf[i] = hrow[i];
        __syncwarp();

        float z = 0.f;
        const float* wrow = sWt + lane * WLT_PITCH;
#pragma unroll 4
        for (int i = 0; i < LIN; i += 4) {
            float4 wv = *(const float4*)(wrow + i);
            float4 bv = *(const float4*)(buf + i);
            z = fmaf(bv.x, wv.x, z);
            z = fmaf(bv.y, wv.y, z);
            z = fmaf(bv.z, wv.z, z);
            z = fmaf(bv.w, wv.w, z);
        }
        float v = (z + sb[lane]) * swp[lane];
#pragma unroll
        for (int o = 16; o > 0; o >>= 1) v += __shfl_xor_sync(0xffffffffu, v, o);
        if (lane == 0) out[g] = 1.f / (1.f + expf(-(v + bp)));
        __syncwarp();   // protect buf before next iteration's loads
    }
}

// ---------------------------------------------------------------------------
extern "C" void kernel_launch(void* const* d_in, const int* in_sizes, int n_in,
                              void* d_out, int out_size)
{
    const float* feature   = (const float*)d_in[0];
    const int*   edges     = (const int*)d_in[1];   // int32 or int64; kernel detects
    const float* W1   = (const float*)d_in[2];
    const float* a_s1 = (const float*)d_in[3];
    const float* a_d1 = (const float*)d_in[4];
    const float* b1   = (const float*)d_in[5];
    const float* W2   = (const float*)d_in[6];
    const float* a_s2 = (const float*)d_in[7];
    const float* a_d2 = (const float*)d_in[8];
    const float* b2   = (const float*)d_in[9];
    const float* Wlin = (const float*)d_in[10];
    const float* blin = (const float*)d_in[11];
    const float* Wprd = (const float*)d_in[12];
    const float* bprd = (const float*)d_in[13];
    float* out = (float*)d_out;

    int sms = 148;
    cudaDeviceGetAttribute(&sms, cudaDevAttrMultiProcessorCount, 0);

    cudaFuncSetAttribute(gat_fused_kernel,
                         cudaFuncAttributeMaxDynamicSharedMemorySize, SMEM_A_BYTES);
    cudaFuncSetAttribute(gat_mlp_kernel,
                         cudaFuncAttributeMaxDynamicSharedMemorySize, MLP_SMEM_BYTES);

    gat_fused_kernel<<<sms, 256, SMEM_A_BYTES>>>(feature, edges, W1, a_s1, a_d1, b1,
                                                 W2, a_s2, a_d2, b2);
    gat_mlp_kernel<<<sms, 256, MLP_SMEM_BYTES>>>(Wlin, blin, Wprd, bprd, out);
}

// round 5
// speedup vs baseline: 1.2678x; 1.2678x over previous
#include <cuda_runtime.h>

#define BG   16384
#define NN   14
#define FIN  128
#define HH   4
#define CC   64
#define HC   256       // H*C
#define EE   182
#define ET   196       // EE + NN self loops
#define LIN  896       // N*C
#define LOUT 32
#define XP   20        // transposed-x pitch (floats); mult of 4 for 16B-aligned LDS.128

// global scratch for h2 between kernels
__device__ float g_h2[(size_t)BG * LIN];

typedef unsigned long long u64;

// ---- packed f32x2 helpers (Blackwell FFMA2 path) ----
__device__ __forceinline__ u64 pk2(float a, float b) {
    u64 r; asm("mov.b64 %0,{%1,%2};" : "=l"(r) : "f"(a), "f"(b)); return r;
}
__device__ __forceinline__ void up2(u64 v, float& a, float& b) {
    asm("mov.b64 {%0,%1},%2;" : "=f"(a), "=f"(b) : "l"(v));
}
__device__ __forceinline__ void fma2(u64& d, u64 a, u64 b) {
    asm("fma.rn.f32x2 %0,%1,%2,%0;" : "+l"(d) : "l"(a), "l"(b));
}

// ---- kernel A smem layout ----
// [0, 32768)        W1  (128 x 256)
// [32768, 49152)    W2  ( 64 x 256)
// per group g (g = 0,1): base = 49152 + g*GBLK
//   +0     REGION 3072: xT (128 x 20) / exchange buf (2x896) ; x2T at +1792 (64 x 20)
//   +3072  sAl  112   [n][h][src,dst]
//   +3184  sDen 56    [d][h]
//   +3240  sA   784   [h][d][s]
//   +4024  sEdge 196 ints
#define GBLK     4224
#define OFF_AL   3072
#define OFF_DEN  3184
#define OFF_AMAT 3240
#define OFF_EDGE 4024
#define SMEM_A_FLOATS (49152 + 2 * GBLK + 4)
#define SMEM_A_BYTES  (SMEM_A_FLOATS * 4)

__device__ __forceinline__ void barg(int bid) {
    asm volatile("bar.sync %0, 256;" :: "r"(bid));
}

// GEMM: acc pairs accp[i] = (h[2i][col], h[2i+1][col]); x transposed [k][n] pitch XP
template <int K>
__device__ __forceinline__ void gemm14(const float* __restrict__ sW,
                                       const float* __restrict__ sxT,
                                       int col, u64* __restrict__ accp)
{
#pragma unroll
    for (int i = 0; i < 7; i++) accp[i] = 0ull;
#pragma unroll 8
    for (int k = 0; k < K; k++) {
        float w = sW[k * HC + col];
        u64 w2 = pk2(w, w);
        const u64* xp = (const u64*)(sxT + k * XP);
        ulonglong2 q01 = *(const ulonglong2*)(xp);
        ulonglong2 q23 = *(const ulonglong2*)(xp + 2);
        ulonglong2 q45 = *(const ulonglong2*)(xp + 4);
        u64 x6 = xp[6];
        fma2(accp[0], q01.x, w2); fma2(accp[1], q01.y, w2);
        fma2(accp[2], q23.x, w2); fma2(accp[3], q23.y, w2);
        fma2(accp[4], q45.x, w2); fma2(accp[5], q45.y, w2);
        fma2(accp[6], x6, w2);
    }
}

// logits (shfl reduce) -> edge pass -> aggregation. Needs scratch zeroed & barrier'd.
__device__ __forceinline__ void attn(float* __restrict__ gb,
                                     const u64* __restrict__ accp,
                                     float as, float ad,
                                     int gtid, int lane, int hh, int bid,
                                     float* __restrict__ aggf)
{
    float* sAl  = gb + OFF_AL;
    float* sDen = gb + OFF_DEN;
    float* sA   = gb + OFF_AMAT;
    const int* sEdge = (const int*)(gb + OFF_EDGE);

    float hc[NN];
#pragma unroll
    for (int i = 0; i < 7; i++) up2(accp[i], hc[2 * i], hc[2 * i + 1]);

    float ps[NN], pd[NN];
#pragma unroll
    for (int n = 0; n < NN; n++) { ps[n] = hc[n] * as; pd[n] = hc[n] * ad; }
#pragma unroll
    for (int o = 16; o > 0; o >>= 1) {
#pragma unroll
        for (int n = 0; n < NN; n++) {
            ps[n] += __shfl_xor_sync(0xffffffffu, ps[n], o);
            pd[n] += __shfl_xor_sync(0xffffffffu, pd[n], o);
        }
    }
    if (lane == 0) {
#pragma unroll
        for (int n = 0; n < NN; n++) {
            atomicAdd(&sAl[n * 8 + hh * 2 + 0], ps[n]);
            atomicAdd(&sAl[n * 8 + hh * 2 + 1], pd[n]);
        }
    }
    barg(bid);

    // single edge pass: accumulate exp into A and denom
    if (gtid < ET) {
        int e = sEdge[gtid];
        int s_ = e & 255, d_ = (e >> 8) & 255;
#pragma unroll
        for (int h = 0; h < HH; h++) {
            float ev = sAl[s_ * 8 + h * 2 + 0] + sAl[d_ * 8 + h * 2 + 1];
            ev = (ev > 0.f) ? ev : 0.2f * ev;
            float ex = expf(ev);
            atomicAdd(&sA[(h * NN + d_) * NN + s_], ex);
            atomicAdd(&sDen[d_ * 4 + h], ex);
        }
    }
    barg(bid);

    // aggregation: agg[n] = (sum_s A[h][n][s] * h[s][col]) / den[n][h]
#pragma unroll
    for (int n = 0; n < NN; n++) {
        const u64* Ar = (const u64*)(sA + (hh * NN + n) * NN);
        u64 t = 0ull;
#pragma unroll
        for (int i = 0; i < 7; i++) fma2(t, Ar[i], accp[i]);
        float tx, ty; up2(t, tx, ty);
        aggf[n] = (tx + ty) * __fdividef(1.f, sDen[n * 4 + hh]);
    }
}

// ---------------------------------------------------------------------------
__global__ __launch_bounds__(512, 1)
void gat_fused_kernel(const float* __restrict__ feature,
                      const int* __restrict__ edge_raw,   // int32 OR int64 (detected)
                      const float* __restrict__ W1, const float* __restrict__ a_s1,
                      const float* __restrict__ a_d1, const float* __restrict__ b1,
                      const float* __restrict__ W2, const float* __restrict__ a_s2,
                      const float* __restrict__ a_d2, const float* __restrict__ b2)
{
    extern __shared__ float sm[];
    float* sW1 = sm;
    float* sW2 = sm + 32768;

    const int tid  = threadIdx.x;
    const int gid  = tid >> 8;        // graph group 0/1
    const int gtid = tid & 255;
    const int lane = tid & 31;
    const int hh   = gtid >> 6;       // head
    const int cch  = gtid & 63;       // channel within head
    const int bid  = gid + 1;         // named barrier id

    float* gb   = sm + 49152 + gid * GBLK;
    float* xT   = gb;                 // [128][XP]
    float* x2T  = gb + 1792;          // [64][XP]
    float* xbuf = gb;                 // exchange buffer [2][896]
    int*   sEdge = (int*)(gb + OFF_EDGE);
    int*   sFlag = (int*)(sm + 49152 + 2 * GBLK);

    // edge dtype detection (int64 high words all zero vs int32 data)
    if (tid == 0) {
        int allz = 1;
        for (int i = 0; i < 64; i++) allz &= (edge_raw[2 * i + 1] == 0);
        *sFlag = allz;
    }
    // preload weights (shared by both groups)
    {
        const float4* w1v = (const float4*)W1;
        float4* d1 = (float4*)sW1;
        for (int i = tid; i < FIN * HC / 4; i += 512) d1[i] = w1v[i];
        const float4* w2v = (const float4*)W2;
        float4* d2 = (float4*)sW2;
        for (int i = tid; i < CC * HC / 4; i += 512) d2[i] = w2v[i];
    }
    // per-thread attention params
    const float as1 = a_s1[gtid], ad1 = a_d1[gtid];
    const float as2 = a_s2[gtid], ad2 = a_d2[gtid];
    const float b1c = b1[cch],    b2c = b2[cch];

    __syncthreads();
    const int is64 = *sFlag;

    for (int g = blockIdx.x * 2 + gid; g < BG; g += gridDim.x * 2) {
        // ---- load x transposed + edges + zero scratch ----
        if (gtid < FIN) {
            const float* fp = feature + (size_t)g * (NN * FIN) + gtid;
#pragma unroll
            for (int n = 0; n < NN; n++) xT[gtid * XP + n] = fp[n * FIN];
        }
        if (gtid < EE) {
            int s, d;
            if (is64) {
                const long long* ep = (const long long*)edge_raw + ((size_t)g * EE + gtid) * 2;
                s = (int)ep[0]; d = (int)ep[1];
            } else {
                const int* ep = edge_raw + ((size_t)g * EE + gtid) * 2;
                s = ep[0]; d = ep[1];
            }
            sEdge[gtid] = s | (d << 8);
        } else if (gtid < ET) {
            int v = gtid - EE;
            sEdge[gtid] = v | (v << 8);
        }
        for (int i = gtid; i < 952; i += 256) gb[OFF_AL + i] = 0.f;
        barg(bid);

        // ---- layer 1 ----
        u64 accp[7];
        float aggf[NN];
        gemm14<FIN>(sW1, xT, gtid, accp);
        attn(gb, accp, as1, ad1, gtid, lane, hh, bid, aggf);

        // head-mean exchange -> relu -> x2T  (xT region is free now)
        if (hh >= 2) {
#pragma unroll
            for (int n = 0; n < NN; n++) xbuf[(hh - 2) * LIN + n * 64 + cch] = aggf[n];
        }
        barg(bid);
        if (hh < 2) {
#pragma unroll
            for (int n = 0; n < NN; n++) aggf[n] += xbuf[hh * LIN + n * 64 + cch];
            if (hh == 1) {
#pragma unroll
                for (int n = 0; n < NN; n++) xbuf[LIN + n * 64 + cch] = aggf[n];
            }
        }
        barg(bid);
        if (hh == 0) {
#pragma unroll
            for (int n = 0; n < NN; n++) {
                float v = 0.25f * (aggf[n] + xbuf[LIN + n * 64 + cch]) + b1c;
                x2T[cch * XP + n] = fmaxf(v, 0.f);
            }
        }
        barg(bid);

        // zero scratch for layer 2 (all reads of sA finished before the bars above)
        for (int i = gtid; i < 952; i += 256) gb[OFF_AL + i] = 0.f;

        // ---- layer 2 ----
        gemm14<CC>(sW2, x2T, gtid, accp);
        barg(bid);   // zeros visible before attn atomics
        attn(gb, accp, as2, ad2, gtid, lane, hh, bid, aggf);

        if (hh >= 2) {
#pragma unroll
            for (int n = 0; n < NN; n++) xbuf[(hh - 2) * LIN + n * 64 + cch] = aggf[n];
        }
        barg(bid);
        if (hh < 2) {
#pragma unroll
            for (int n = 0; n < NN; n++) aggf[n] += xbuf[hh * LIN + n * 64 + cch];
            if (hh == 1) {
#pragma unroll
                for (int n = 0; n < NN; n++) xbuf[LIN + n * 64 + cch] = aggf[n];
            }
        }
        barg(bid);
        if (hh == 0) {
            float* orow = g_h2 + (size_t)g * LIN;
#pragma unroll
            for (int n = 0; n < NN; n++)
                orow[n * 64 + cch] = 0.25f * (aggf[n] + xbuf[LIN + n * 64 + cch]) + b2c;
        }
        barg(bid);   // protect xbuf/xT/sEdge before next iteration
    }
}

// ---------------------------------------------------------------------------
// kernel B: z = h2 @ W_lin + b_lin ; p = z @ W_pred + b_pred ; out = sigmoid(p)
// 512 threads, one warp per graph (16 graphs/iter); W_lin transposed in smem.
// ---------------------------------------------------------------------------
#define WLT_PITCH 900
#define MLP_SMEM_FLOATS (LOUT * WLT_PITCH + 16 * LIN + 64)
#define MLP_SMEM_BYTES  (MLP_SMEM_FLOATS * 4)

__global__ __launch_bounds__(512, 1)
void gat_mlp_kernel(const float* __restrict__ Wlin, const float* __restrict__ blin,
                    const float* __restrict__ Wpred, const float* __restrict__ bpred,
                    float* __restrict__ out)
{
    extern __shared__ float sm[];
    float* sWt  = sm;                           // [32][900]
    float* sbuf = sm + LOUT * WLT_PITCH;        // [16][896]
    float* sb   = sbuf + 16 * LIN;              // [32]
    float* swp  = sb + LOUT;                    // [32]

    const int tid = threadIdx.x;
    const int lane = tid & 31;
    const int w = tid >> 5;

    for (int i = tid; i < LIN * LOUT; i += 512) {
        int r = i >> 5, c = i & 31;             // Wlin[r][c], LOUT=32
        sWt[c * WLT_PITCH + r] = Wlin[i];
    }
    if (tid < LOUT) { sb[tid] = blin[tid]; swp[tid] = Wpred[tid]; }
    __syncthreads();
    const float bp = bpred[0];

    for (int g = blockIdx.x * 16 + w; g < BG; g += gridDim.x * 16) {
        const float* hrow = g_h2 + (size_t)g * LIN;
        float* buf = sbuf + w * LIN;
        for (int i = lane * 4; i < LIN; i += 128)
            *(float4*)(buf + i) = *(const float4*)(hrow + i);
        __syncwarp();

        u64 z2 = 0ull;
        const float* wr = sWt + lane * WLT_PITCH;
#pragma unroll 4
        for (int i = 0; i < LIN; i += 4) {
            ulonglong2 wq = *(const ulonglong2*)(wr + i);
            ulonglong2 bq = *(const ulonglong2*)(buf + i);
            fma2(z2, wq.x, bq.x);
            fma2(z2, wq.y, bq.y);
        }
        float zx, zy; up2(z2, zx, zy);
        float v = (zx + zy + sb[lane]) * swp[lane];
#pragma unroll
        for (int o = 16; o > 0; o >>= 1) v += __shfl_xor_sync(0xffffffffu, v, o);
        if (lane == 0) out[g] = 1.f / (1.f + expf(-(v + bp)));
        __syncwarp();
    }
}

// ---------------------------------------------------------------------------
extern "C" void kernel_launch(void* const* d_in, const int* in_sizes, int n_in,
                              void* d_out, int out_size)
{
    const float* feature = (const float*)d_in[0];
    const int*   edges   = (const int*)d_in[1];
    const float* W1   = (const float*)d_in[2];
    const float* a_s1 = (const float*)d_in[3];
    const float* a_d1 = (const float*)d_in[4];
    const float* b1   = (const float*)d_in[5];
    const float* W2   = (const float*)d_in[6];
    const float* a_s2 = (const float*)d_in[7];
    const float* a_d2 = (const float*)d_in[8];
    const float* b2   = (const float*)d_in[9];
    const float* Wlin = (const float*)d_in[10];
    const float* blin = (const float*)d_in[11];
    const float* Wprd = (const float*)d_in[12];
    const float* bprd = (const float*)d_in[13];
    float* out = (float*)d_out;

    int sms = 148;
    cudaDeviceGetAttribute(&sms, cudaDevAttrMultiProcessorCount, 0);

    cudaFuncSetAttribute(gat_fused_kernel,
                         cudaFuncAttributeMaxDynamicSharedMemorySize, SMEM_A_BYTES);
    cudaFuncSetAttribute(gat_mlp_kernel,
                         cudaFuncAttributeMaxDynamicSharedMemorySize, MLP_SMEM_BYTES);

    gat_fused_kernel<<<sms, 512, SMEM_A_BYTES>>>(feature, edges, W1, a_s1, a_d1, b1,
                                                 W2, a_s2, a_d2, b2);
    gat_mlp_kernel<<<sms, 512, MLP_SMEM_BYTES>>>(Wlin, blin, Wprd, bprd, out);
}

// round 9
// speedup vs baseline: 1.5714x; 1.2395x over previous
#include <cuda_runtime.h>

#define BG   16384
#define NN   14
#define FIN  128
#define HH   4
#define CC   64
#define HC   256       // H*C
#define EE   182
#define ET   196       // EE + NN self loops
#define LIN  896       // N*C
#define LOUT 32
#define XP   20        // transposed-x pitch (floats); mult of 4 for 16B-aligned LDS.128

// global scratch for h2 between kernels
__device__ float g_h2[(size_t)BG * LIN];

typedef unsigned long long u64;

// ---- packed f32x2 helpers (Blackwell FFMA2/FADD2 path) ----
__device__ __forceinline__ u64 pk2(float a, float b) {
    u64 r; asm("mov.b64 %0,{%1,%2};" : "=l"(r) : "f"(a), "f"(b)); return r;
}
__device__ __forceinline__ void up2(u64 v, float& a, float& b) {
    asm("mov.b64 {%0,%1},%2;" : "=f"(a), "=f"(b) : "l"(v));
}
__device__ __forceinline__ void fma2(u64& d, u64 a, u64 b) {
    asm("fma.rn.f32x2 %0,%1,%2,%0;" : "+l"(d) : "l"(a), "l"(b));
}
__device__ __forceinline__ void add2(u64& d, u64 a) {
    asm("add.rn.f32x2 %0,%0,%1;" : "+l"(d) : "l"(a));
}

// ---- kernel A smem layout (float offsets) ----
// [0,32768)      W1 (128 x 256)
// [32768,49152)  W2 (64 x 256)
// [49152,50176)  wa1 [128][8]  (h*2+sd)
// [50176,50688)  wa2 [64][8]
// per group: base = 50688 + gid*GBLK
//   +0     xT [128][20] (2560)   — exch (896) overlays +0; x2T (64x20) overlays +1280
//   +2560  sAl 112   [n][h][s,d]
//   +2672  sA  784   [h][d][s]
//   +3456  edges 196 ints
#define GBLK      3656
#define OFF_AL    2560
#define OFF_AMAT  2672
#define OFF_EDGE  3456
#define OFF_WA1   49152
#define OFF_WA2   50176
#define GRP_BASE  50688
#define SMEM_A_FLOATS (GRP_BASE + 2 * GBLK + 4)
#define SMEM_A_BYTES  (SMEM_A_FLOATS * 4)   // 232016 <= 232448

__device__ __forceinline__ void barg(int bid) {
    asm volatile("bar.sync %0, 256;" :: "r"(bid));
}

// GEMM: accp[i] = (h[2i][col], h[2i+1][col]); x transposed [k][n] pitch XP
template <int K>
__device__ __forceinline__ void gemm14(const float* __restrict__ sW,
                                       const float* __restrict__ sxT,
                                       int col, u64* __restrict__ accp)
{
#pragma unroll
    for (int i = 0; i < 7; i++) accp[i] = 0ull;
#pragma unroll 4
    for (int k = 0; k < K; k++) {
        float w = sW[k * HC + col];
        u64 w2 = pk2(w, w);
        const u64* xp = (const u64*)(sxT + k * XP);
        ulonglong2 q01 = *(const ulonglong2*)(xp);
        ulonglong2 q23 = *(const ulonglong2*)(xp + 2);
        ulonglong2 q45 = *(const ulonglong2*)(xp + 4);
        u64 x6 = xp[6];
        fma2(accp[0], q01.x, w2); fma2(accp[1], q01.y, w2);
        fma2(accp[2], q23.x, w2); fma2(accp[3], q23.y, w2);
        fma2(accp[4], q45.x, w2); fma2(accp[5], q45.y, w2);
        fma2(accp[6], x6, w2);
    }
}

// logits from precomputed wa: sAl[n*8+hs] = sum_k xT[k][n]*wa[k][hs]
// 8 warps x 14 lanes cover all 112 entries; direct store, no atomics.
template <int K>
__device__ __forceinline__ void logits(const float* __restrict__ sxT,
                                       const float* __restrict__ wa,
                                       float* __restrict__ sAl,
                                       int gtid, int lane)
{
    if (lane < 14) {
        int idx = (gtid >> 5) * 14 + lane;   // 0..111
        int n = idx >> 3, hs = idx & 7;
        float acc = 0.f;
#pragma unroll 4
        for (int k = 0; k < K; k++)
            acc = fmaf(sxT[k * XP + n], wa[k * 8 + hs], acc);
        sAl[n * 8 + hs] = acc;
    }
}

// edge pass: exp(leakyrelu(logit)) accumulated into dense A[h][d][s]
__device__ __forceinline__ void edge_pass(const float* __restrict__ sAl,
                                          float* __restrict__ sA,
                                          const int* __restrict__ sEdge, int gtid)
{
    if (gtid < ET) {
        int e = sEdge[gtid];
        int s_ = e & 255, d_ = (e >> 8) & 255;
#pragma unroll
        for (int h = 0; h < HH; h++) {
            float ev = sAl[s_ * 8 + h * 2 + 0] + sAl[d_ * 8 + h * 2 + 1];
            ev = (ev > 0.f) ? ev : 0.2f * ev;
            atomicAdd(&sA[(h * NN + d_) * NN + s_], __expf(ev));
        }
    }
}

// aggregation: aggf[n] = (sum_s A[h][n][s]*h[s][col]) / rowsum(A[h][n]);
// then accumulate into the head-sum exchange buffer.
__device__ __forceinline__ void agg_exch(const float* __restrict__ sA,
                                         const u64* __restrict__ accp,
                                         float* __restrict__ exch,
                                         int hh, int cch)
{
#pragma unroll
    for (int n = 0; n < NN; n++) {
        const u64* Ar = (const u64*)(sA + (hh * NN + n) * NN);
        u64 t = 0ull, dn = 0ull;
#pragma unroll
        for (int i = 0; i < 7; i++) { u64 a = Ar[i]; fma2(t, a, accp[i]); add2(dn, a); }
        float tx, ty, dx, dy;
        up2(t, tx, ty); up2(dn, dx, dy);
        atomicAdd(&exch[n * 64 + cch], __fdividef(tx + ty, dx + dy));
    }
}

// ---------------------------------------------------------------------------
__global__ __launch_bounds__(512, 1)
void gat_fused_kernel(const float* __restrict__ feature,
                      const int* __restrict__ edge_raw,   // int32 OR int64 (detected)
                      const float* __restrict__ W1, const float* __restrict__ a_s1,
                      const float* __restrict__ a_d1, const float* __restrict__ b1,
                      const float* __restrict__ W2, const float* __restrict__ a_s2,
                      const float* __restrict__ a_d2, const float* __restrict__ b2)
{
    extern __shared__ float sm[];
    float* sW1 = sm;
    float* sW2 = sm + 32768;
    float* wa1 = sm + OFF_WA1;
    float* wa2 = sm + OFF_WA2;

    const int tid  = threadIdx.x;
    const int gid  = tid >> 8;
    const int gtid = tid & 255;
    const int lane = tid & 31;
    const int hh   = gtid >> 6;
    const int cch  = gtid & 63;
    const int bid  = gid + 1;

    float* gb    = sm + GRP_BASE + gid * GBLK;
    float* xT    = gb;                 // [128][XP]
    float* exch  = gb;                 // overlays xT[0..896)   (live after xT dead)
    float* x2T   = gb + 1280;          // overlays xT[1280..2560)
    float* sAl   = gb + OFF_AL;
    float* sA    = gb + OFF_AMAT;
    int*   sEdge = (int*)(gb + OFF_EDGE);
    int*   sFlag = (int*)(sm + GRP_BASE + 2 * GBLK);

    if (tid == 0) {
        int allz = 1;
        for (int i = 0; i < 64; i++) allz &= (edge_raw[2 * i + 1] == 0);
        *sFlag = allz;
    }
    // preload weights (shared by both groups)
    {
        const float4* w1v = (const float4*)W1;
        float4* d1 = (float4*)sW1;
        for (int i = tid; i < FIN * HC / 4; i += 512) d1[i] = w1v[i];
        const float4* w2v = (const float4*)W2;
        float4* d2 = (float4*)sW2;
        for (int i = tid; i < CC * HC / 4; i += 512) d2[i] = w2v[i];
    }
    __syncthreads();

    // precompute wa1[k][h*2+sd] = sum_c W1[k][h*64+c]*a_{s,d}1[h*64+c]  (2/thread)
    for (int j = 0; j < 2; j++) {
        int idx = tid * 2 + j;               // 0..1023
        int k = idx >> 3, hs = idx & 7, h = hs >> 1;
        const float* av = (hs & 1) ? a_d1 : a_s1;
        const float* wr = sW1 + k * HC + h * CC;
        const float* ar = av + h * CC;
        float acc = 0.f;
#pragma unroll 8
        for (int c = 0; c < CC; c++) acc = fmaf(wr[c], ar[c], acc);
        wa1[idx] = acc;
    }
    {   // wa2: 512 entries, 1/thread
        int idx = tid;
        int k = idx >> 3, hs = idx & 7, h = hs >> 1;
        const float* av = (hs & 1) ? a_d2 : a_s2;
        const float* wr = sW2 + k * HC + h * CC;
        const float* ar = av + h * CC;
        float acc = 0.f;
#pragma unroll 8
        for (int c = 0; c < CC; c++) acc = fmaf(wr[c], ar[c], acc);
        wa2[idx] = acc;
    }
    const float b1c = b1[cch], b2c = b2[cch];
    __syncthreads();
    const int is64 = *sFlag;

    for (int g = blockIdx.x * 2 + gid; g < BG; g += gridDim.x * 2) {
        // ---- load xT + edges, zero A ----
        if (gtid < FIN) {
            const float* fp = feature + (size_t)g * (NN * FIN) + gtid;
#pragma unroll
            for (int n = 0; n < NN; n++) xT[gtid * XP + n] = fp[n * FIN];
        }
        if (gtid < EE) {
            int s, d;
            if (is64) {
                const long long* ep = (const long long*)edge_raw + ((size_t)g * EE + gtid) * 2;
                s = (int)ep[0]; d = (int)ep[1];
            } else {
                const int* ep = edge_raw + ((size_t)g * EE + gtid) * 2;
                s = ep[0]; d = ep[1];
            }
            sEdge[gtid] = s | (d << 8);
        } else if (gtid < ET) {
            int v = gtid - EE;
            sEdge[gtid] = v | (v << 8);
        }
        for (int i = gtid; i < HH * NN * NN; i += 256) sA[i] = 0.f;
        barg(bid);                                        // bar1

        // ---- layer 1 ----
        u64 accp[7];
        gemm14<FIN>(sW1, xT, gtid, accp);
        logits<FIN>(xT, wa1, sAl, gtid, lane);
        barg(bid);                                        // bar2 (xT dead after this)

        for (int i = gtid; i < LIN; i += 256) exch[i] = 0.f;   // exch overlays xT[0..896)
        edge_pass(sAl, sA, sEdge, gtid);
        barg(bid);                                        // bar3

        agg_exch(sA, accp, exch, hh, cch);
        barg(bid);                                        // bar4

        if (gtid < CC) {                                  // build x2T = relu(mean + b1)
#pragma unroll
            for (int n = 0; n < NN; n++) {
                float v = 0.25f * exch[n * 64 + gtid] + b1c;
                x2T[gtid * XP + n] = fmaxf(v, 0.f);
            }
        }
        barg(bid);                                        // bar5

        // ---- layer 2 ----
        for (int i = gtid; i < HH * NN * NN; i += 256) sA[i] = 0.f;
        gemm14<CC>(sW2, x2T, gtid, accp);
        logits<CC>(x2T, wa2, sAl, gtid, lane);
        barg(bid);                                        // bar6

        for (int i = gtid; i < LIN; i += 256) exch[i] = 0.f;
        edge_pass(sAl, sA, sEdge, gtid);
        barg(bid);                                        // bar7

        agg_exch(sA, accp, exch, hh, cch);
        barg(bid);                                        // bar8

        if (gtid < CC) {
            float* orow = g_h2 + (size_t)g * LIN;
#pragma unroll
            for (int n = 0; n < NN; n++)
                orow[n * 64 + gtid] = 0.25f * exch[n * 64 + gtid] + b2c;
        }
        barg(bid);                                        // bar9 (protect smem reuse)
    }
}

// ---------------------------------------------------------------------------
// kernel B: z = h2 @ W_lin + b_lin ; p = z @ W_pred + b_pred ; out = sigmoid(p)
// 1024 threads (32 warps/SM), one warp per graph, chunked per-warp h buffer.
// ---------------------------------------------------------------------------
#define WLT_PITCH 900
#define CHUNK 448
#define MLP_SMEM_FLOATS (LOUT * WLT_PITCH + 32 * CHUNK + 64)
#define MLP_SMEM_BYTES  (MLP_SMEM_FLOATS * 4)   // 172,800 B

__global__ __launch_bounds__(1024, 1)
void gat_mlp_kernel(const float* __restrict__ Wlin, const float* __restrict__ blin,
                    const float* __restrict__ Wpred, const float* __restrict__ bpred,
                    float* __restrict__ out)
{
    extern __shared__ float sm[];
    float* sWt  = sm;                           // [32][900]
    float* sbuf = sm + LOUT * WLT_PITCH;        // [32][448]
    float* sb   = sbuf + 32 * CHUNK;            // [32]
    float* swp  = sb + LOUT;                    // [32]

    const int tid = threadIdx.x;
    const int lane = tid & 31;
    const int w = tid >> 5;

    for (int i = tid; i < LIN * LOUT; i += 1024) {
        int r = i >> 5, c = i & 31;             // Wlin[r][c]
        sWt[c * WLT_PITCH + r] = Wlin[i];
    }
    if (tid < LOUT) { sb[tid] = blin[tid]; swp[tid] = Wpred[tid]; }
    __syncthreads();
    const float bp = bpred[0];

    float* buf = sbuf + w * CHUNK;
    for (int g = blockIdx.x * 32 + w; g < BG; g += gridDim.x * 32) {
        const float* hrow = g_h2 + (size_t)g * LIN;
        u64 z2 = 0ull;
#pragma unroll
        for (int ch = 0; ch < 2; ch++) {
            for (int i = lane * 4; i < CHUNK; i += 128)
                *(float4*)(buf + i) = *(const float4*)(hrow + ch * CHUNK + i);
            __syncwarp();
            const float* wr = sWt + lane * WLT_PITCH + ch * CHUNK;
#pragma unroll 4
            for (int i = 0; i < CHUNK; i += 4) {
                ulonglong2 wq = *(const ulonglong2*)(wr + i);
                ulonglong2 bq = *(const ulonglong2*)(buf + i);
                fma2(z2, wq.x, bq.x);
                fma2(z2, wq.y, bq.y);
            }
            __syncwarp();
        }
        float zx, zy; up2(z2, zx, zy);
        float v = (zx + zy + sb[lane]) * swp[lane];
#pragma unroll
        for (int o = 16; o > 0; o >>= 1) v += __shfl_xor_sync(0xffffffffu, v, o);
        if (lane == 0) out[g] = 1.f / (1.f + expf(-(v + bp)));
    }
}

// ---------------------------------------------------------------------------
extern "C" void kernel_launch(void* const* d_in, const int* in_sizes, int n_in,
                              void* d_out, int out_size)
{
    const float* feature = (const float*)d_in[0];
    const int*   edges   = (const int*)d_in[1];
    const float* W1   = (const float*)d_in[2];
    const float* a_s1 = (const float*)d_in[3];
    const float* a_d1 = (const float*)d_in[4];
    const float* b1   = (const float*)d_in[5];
    const float* W2   = (const float*)d_in[6];
    const float* a_s2 = (const float*)d_in[7];
    const float* a_d2 = (const float*)d_in[8];
    const float* b2   = (const float*)d_in[9];
    const float* Wlin = (const float*)d_in[10];
    const float* blin = (const float*)d_in[11];
    const float* Wprd = (const float*)d_in[12];
    const float* bprd = (const float*)d_in[13];
    float* out = (float*)d_out;

    int sms = 148;
    cudaDeviceGetAttribute(&sms, cudaDevAttrMultiProcessorCount, 0);

    cudaFuncSetAttribute(gat_fused_kernel,
                         cudaFuncAttributeMaxDynamicSharedMemorySize, SMEM_A_BYTES);
    cudaFuncSetAttribute(gat_mlp_kernel,
                         cudaFuncAttributeMaxDynamicSharedMemorySize, MLP_SMEM_BYTES);

    gat_fused_kernel<<<sms, 512, SMEM_A_BYTES>>>(feature, edges, W1, a_s1, a_d1, b1,
                                                 W2, a_s2, a_d2, b2);
    gat_mlp_kernel<<<sms, 1024, MLP_SMEM_BYTES>>>(Wlin, blin, Wprd, bprd, out);
}

// round 11
// speedup vs baseline: 1.7072x; 1.0864x over previous
#include <cuda_runtime.h>

#define BG   16384
#define NN   14
#define FIN  128
#define HH   4
#define CC   64
#define HC   256       // H*C
#define EE   182
#define ET   196       // EE + NN self loops
#define LIN  896       // N*C
#define LOUT 32
#define XP   20        // transposed-x pitch (floats)

// global scratch for h2 between kernels
__device__ __align__(16) float g_h2[(size_t)BG * LIN];

typedef unsigned long long u64;

// ---- packed f32x2 helpers (Blackwell FFMA2/FADD2 path) ----
__device__ __forceinline__ u64 pk2(float a, float b) {
    u64 r; asm("mov.b64 %0,{%1,%2};" : "=l"(r) : "f"(a), "f"(b)); return r;
}
__device__ __forceinline__ void up2(u64 v, float& a, float& b) {
    asm("mov.b64 {%0,%1},%2;" : "=f"(a), "=f"(b) : "l"(v));
}
__device__ __forceinline__ void fma2(u64& d, u64 a, u64 b) {
    asm("fma.rn.f32x2 %0,%1,%2,%0;" : "+l"(d) : "l"(a), "l"(b));
}
__device__ __forceinline__ void add2(u64& d, u64 a) {
    asm("add.rn.f32x2 %0,%0,%1;" : "+l"(d) : "l"(a));
}

// ---- kernel A smem layout (float offsets) ----
// [0,32768)      W1 (128 x 256)
// [32768,49152)  W2 (64 x 256)
// [49152,50176)  wa1 [128][8]
// [50176,50688)  wa2 [64][8]
// per group: base = 50688 + gid*GBLK   (GBLK multiple of 4 -> 16B alignment!)
//   +0     region R (2688): xT [128][20]=2560 | shh [3][896]=2688 | x2T [64][20]=1280
//   +2688  sAl 112   [n][h][s,d]
//   +2800  sA  784   [h][d][s]
//   +3584  edges: 196 u16 (98 floats) + 2 pad
#define GBLK      3684
#define OFF_AL    2688
#define OFF_AMAT  2800
#define OFF_EDGE  3584
#define OFF_WA1   49152
#define OFF_WA2   50176
#define GRP_BASE  50688
#define SMEM_A_FLOATS (GRP_BASE + 2 * GBLK + 4)
#define SMEM_A_BYTES  (SMEM_A_FLOATS * 4)   // 232240 <= 232448

__device__ __forceinline__ void barg(int bid) {
    asm volatile("bar.sync %0, 256;" :: "r"(bid));
}

// GEMM: accp[i] = (h[2i][col], h[2i+1][col]); x transposed [k][n] pitch XP
template <int K>
__device__ __forceinline__ void gemm14(const float* __restrict__ sW,
                                       const float* __restrict__ sxT,
                                       int col, u64* __restrict__ accp)
{
#pragma unroll
    for (int i = 0; i < 7; i++) accp[i] = 0ull;
#pragma unroll 4
    for (int k = 0; k < K; k++) {
        float w = sW[k * HC + col];
        u64 w2 = pk2(w, w);
        const u64* xp = (const u64*)(sxT + k * XP);
        ulonglong2 q01 = *(const ulonglong2*)(xp);
        ulonglong2 q23 = *(const ulonglong2*)(xp + 2);
        ulonglong2 q45 = *(const ulonglong2*)(xp + 4);
        u64 x6 = xp[6];
        fma2(accp[0], q01.x, w2); fma2(accp[1], q01.y, w2);
        fma2(accp[2], q23.x, w2); fma2(accp[3], q23.y, w2);
        fma2(accp[4], q45.x, w2); fma2(accp[5], q45.y, w2);
        fma2(accp[6], x6, w2);
    }
}

// logits: sAl[n*8+hs] = sum_k xT[k][n]*wa[k][hs]; 8 warps x 14 lanes cover 112.
template <int K>
__device__ __forceinline__ void logits(const float* __restrict__ sxT,
                                       const float* __restrict__ wa,
                                       float* __restrict__ sAl,
                                       int gtid, int lane)
{
    if (lane < 14) {
        int idx = (gtid >> 5) * 14 + lane;   // 0..111
        int n = idx >> 3, hs = idx & 7;
        float acc = 0.f;
#pragma unroll 4
        for (int k = 0; k < K; k++)
            acc = fmaf(sxT[k * XP + n], wa[k * 8 + hs], acc);
        sAl[n * 8 + hs] = acc;
    }
}

// edge pass: exp(leakyrelu(logit)) accumulated into dense A[h][d][s]
__device__ __forceinline__ void edge_pass(const float* __restrict__ sAl,
                                          float* __restrict__ sA,
                                          const unsigned short* __restrict__ sEdge,
                                          int gtid)
{
    if (gtid < ET) {
        int e = sEdge[gtid];
        int s_ = e & 255, d_ = (e >> 8) & 255;
#pragma unroll
        for (int h = 0; h < HH; h++) {
            float ev = sAl[s_ * 8 + h * 2 + 0] + sAl[d_ * 8 + h * 2 + 1];
            ev = (ev > 0.f) ? ev : 0.2f * ev;
            atomicAdd(&sA[(h * NN + d_) * NN + s_], __expf(ev));
        }
    }
}

// aggregation (softmax folded): aggf[n] = (sum_s A[h][n][s]*h[s][col]) / rowsum;
// heads 1..3 publish to shh, head 0 keeps registers.
__device__ __forceinline__ void agg_heads(const float* __restrict__ sA,
                                          const u64* __restrict__ accp,
                                          float* __restrict__ shh,
                                          float* __restrict__ aggf,
                                          int hh, int cch)
{
#pragma unroll
    for (int n = 0; n < NN; n++) {
        const u64* Ar = (const u64*)(sA + (hh * NN + n) * NN);
        u64 t = 0ull, dn = 0ull;
#pragma unroll
        for (int i = 0; i < 7; i++) { u64 a = Ar[i]; fma2(t, a, accp[i]); add2(dn, a); }
        float tx, ty, dx, dy;
        up2(t, tx, ty); up2(dn, dx, dy);
        aggf[n] = __fdividef(tx + ty, dx + dy);
    }
    if (hh > 0) {
        float* dst = shh + (hh - 1) * LIN + cch;
#pragma unroll
        for (int n = 0; n < NN; n++) dst[n * 64] = aggf[n];
    }
}

// head-0 fold: aggf[n] = 0.25*(aggf[n] + 3 slots) + bias
__device__ __forceinline__ void fold_heads(const float* __restrict__ shh,
                                           float* __restrict__ aggf,
                                           float bc, int cch)
{
#pragma unroll
    for (int n = 0; n < NN; n++) {
        float s = aggf[n] + shh[n * 64 + cch] + shh[LIN + n * 64 + cch]
                + shh[2 * LIN + n * 64 + cch];
        aggf[n] = 0.25f * s + bc;
    }
}

// ---------------------------------------------------------------------------
__global__ __launch_bounds__(512, 1)
void gat_fused_kernel(const float* __restrict__ feature,
                      const int* __restrict__ edge_raw,   // int32 OR int64 (detected)
                      const float* __restrict__ W1, const float* __restrict__ a_s1,
                      const float* __restrict__ a_d1, const float* __restrict__ b1,
                      const float* __restrict__ W2, const float* __restrict__ a_s2,
                      const float* __restrict__ a_d2, const float* __restrict__ b2)
{
    extern __shared__ float sm[];
    float* sW1 = sm;
    float* sW2 = sm + 32768;
    float* wa1 = sm + OFF_WA1;
    float* wa2 = sm + OFF_WA2;

    const int tid  = threadIdx.x;
    const int gid  = tid >> 8;
    const int gtid = tid & 255;
    const int lane = tid & 31;
    const int hh   = gtid >> 6;
    const int cch  = gtid & 63;
    const int bid  = gid + 1;

    float* gb    = sm + GRP_BASE + gid * GBLK;
    float* xT    = gb;                 // [128][XP]
    float* shh   = gb;                 // [3][896] overlays xT after it dies
    float* x2T   = gb;                 // [64][XP] overlays (fenced by barriers)
    float* sAl   = gb + OFF_AL;
    float* sA    = gb + OFF_AMAT;
    unsigned short* sEdge = (unsigned short*)(gb + OFF_EDGE);
    int*   sFlag = (int*)(sm + GRP_BASE + 2 * GBLK);

    if (tid == 0) {
        int allz = 1;
        for (int i = 0; i < 64; i++) allz &= (edge_raw[2 * i + 1] == 0);
        *sFlag = allz;
    }
    // preload weights (shared by both groups)
    {
        const float4* w1v = (const float4*)W1;
        float4* d1 = (float4*)sW1;
        for (int i = tid; i < FIN * HC / 4; i += 512) d1[i] = w1v[i];
        const float4* w2v = (const float4*)W2;
        float4* d2 = (float4*)sW2;
        for (int i = tid; i < CC * HC / 4; i += 512) d2[i] = w2v[i];
    }
    __syncthreads();

    // precompute wa1[k][h*2+sd] = sum_c W1[k][h*64+c]*a_{s,d}1[h*64+c]
    for (int j = 0; j < 2; j++) {
        int idx = tid * 2 + j;               // 0..1023
        int k = idx >> 3, hs = idx & 7, h = hs >> 1;
        const float* av = (hs & 1) ? a_d1 : a_s1;
        const float* wr = sW1 + k * HC + h * CC;
        const float* ar = av + h * CC;
        float acc = 0.f;
#pragma unroll 8
        for (int c = 0; c < CC; c++) acc = fmaf(wr[c], ar[c], acc);
        wa1[idx] = acc;
    }
    {   // wa2: 512 entries
        int idx = tid;
        int k = idx >> 3, hs = idx & 7, h = hs >> 1;
        const float* av = (hs & 1) ? a_d2 : a_s2;
        const float* wr = sW2 + k * HC + h * CC;
        const float* ar = av + h * CC;
        float acc = 0.f;
#pragma unroll 8
        for (int c = 0; c < CC; c++) acc = fmaf(wr[c], ar[c], acc);
        wa2[idx] = acc;
    }
    const float b1c = b1[cch], b2c = b2[cch];
    __syncthreads();
    const int is64 = *sFlag;

    for (int g = blockIdx.x * 2 + gid; g < BG; g += gridDim.x * 2) {
        // ---- load xT + edges, zero A ----
        if (gtid < FIN) {
            const float* fp = feature + (size_t)g * (NN * FIN) + gtid;
#pragma unroll
            for (int n = 0; n < NN; n++) xT[gtid * XP + n] = fp[n * FIN];
        }
        if (gtid < EE) {
            int s, d;
            if (is64) {
                const long long* ep = (const long long*)edge_raw + ((size_t)g * EE + gtid) * 2;
                s = (int)ep[0]; d = (int)ep[1];
            } else {
                const int* ep = edge_raw + ((size_t)g * EE + gtid) * 2;
                s = ep[0]; d = ep[1];
            }
            sEdge[gtid] = (unsigned short)(s | (d << 8));
        } else if (gtid < ET) {
            int v = gtid - EE;
            sEdge[gtid] = (unsigned short)(v | (v << 8));
        }
        for (int i = gtid; i < HH * NN * NN; i += 256) sA[i] = 0.f;
        barg(bid);                                        // bar1

        // ---- layer 1 ----
        u64 accp[7];
        float aggf[NN];
        gemm14<FIN>(sW1, xT, gtid, accp);
        logits<FIN>(xT, wa1, sAl, gtid, lane);
        barg(bid);                                        // bar2 (xT dead)

        edge_pass(sAl, sA, sEdge, gtid);
        barg(bid);                                        // bar3

        agg_heads(sA, accp, shh, aggf, hh, cch);
        barg(bid);                                        // bar4

        // head0 folds into regs; everyone zeroes sA for layer 2
        if (hh == 0) fold_heads(shh, aggf, b1c, cch);
        for (int i = gtid; i < HH * NN * NN; i += 256) sA[i] = 0.f;
        barg(bid);                                        // bar5 (shh reads done)

        if (hh == 0) {
#pragma unroll
            for (int n = 0; n < NN; n++) x2T[cch * XP + n] = fmaxf(aggf[n], 0.f);
        }
        barg(bid);                                        // bar6 (x2T ready)

        // ---- layer 2 ----
        gemm14<CC>(sW2, x2T, gtid, accp);
        logits<CC>(x2T, wa2, sAl, gtid, lane);
        barg(bid);                                        // bar7 (x2T dead)

        edge_pass(sAl, sA, sEdge, gtid);
        barg(bid);                                        // bar8

        agg_heads(sA, accp, shh, aggf, hh, cch);
        barg(bid);                                        // bar9

        if (hh == 0) {
            fold_heads(shh, aggf, b2c, cch);
            float* orow = g_h2 + (size_t)g * LIN;
#pragma unroll
            for (int n = 0; n < NN; n++) orow[n * 64 + cch] = aggf[n];
        }
        barg(bid);                                        // bar10 (protect R)
    }
}

// ---------------------------------------------------------------------------
// kernel B: z = h2 @ W_lin + b_lin ; p = z @ W_pred + b_pred ; out = sigmoid(p)
// 1024 threads; each warp processes 4 graphs per pass (W_lin smem reuse x4);
// h rows read straight from gmem as broadcast LDG.128.
// ---------------------------------------------------------------------------
#define WLT_PITCH 900
#define MLP_SMEM_FLOATS (LOUT * WLT_PITCH + 64)
#define MLP_SMEM_BYTES  (MLP_SMEM_FLOATS * 4)   // 115,456 B

__global__ __launch_bounds__(1024, 1)
void gat_mlp_kernel(const float* __restrict__ Wlin, const float* __restrict__ blin,
                    const float* __restrict__ Wpred, const float* __restrict__ bpred,
                    float* __restrict__ out)
{
    extern __shared__ float sm[];
    float* sWt = sm;                            // [32][900]
    float* sb  = sm + LOUT * WLT_PITCH;         // [32]
    float* swp = sb + LOUT;                     // [32]

    const int tid = threadIdx.x;
    const int lane = tid & 31;
    const int w = tid >> 5;

    for (int i = tid; i < LIN * LOUT; i += 1024) {
        int r = i >> 5, c = i & 31;             // Wlin[r][c]
        sWt[c * WLT_PITCH + r] = Wlin[i];
    }
    if (tid < LOUT) { sb[tid] = blin[tid]; swp[tid] = Wpred[tid]; }
    __syncthreads();
    const float bp = bpred[0];

    const float* wr = sWt + lane * WLT_PITCH;
    for (int g0 = (blockIdx.x * 32 + w) * 4; g0 < BG; g0 += gridDim.x * 32 * 4) {
        const float* h0 = g_h2 + (size_t)g0 * LIN;
        const float* h1 = h0 + LIN;
        const float* h2 = h0 + 2 * LIN;
        const float* h3 = h0 + 3 * LIN;
        u64 z0 = 0ull, z1 = 0ull, z2 = 0ull, z3 = 0ull;
#pragma unroll 4
        for (int i = 0; i < LIN; i += 4) {
            ulonglong2 wq = *(const ulonglong2*)(wr + i);
            ulonglong2 a0 = *(const ulonglong2*)(h0 + i);
            ulonglong2 a1 = *(const ulonglong2*)(h1 + i);
            ulonglong2 a2 = *(const ulonglong2*)(h2 + i);
            ulonglong2 a3 = *(const ulonglong2*)(h3 + i);
            fma2(z0, wq.x, a0.x); fma2(z0, wq.y, a0.y);
            fma2(z1, wq.x, a1.x); fma2(z1, wq.y, a1.y);
            fma2(z2, wq.x, a2.x); fma2(z2, wq.y, a2.y);
            fma2(z3, wq.x, a3.x); fma2(z3, wq.y, a3.y);
        }
        u64 zz[4] = {z0, z1, z2, z3};
#pragma unroll
        for (int q = 0; q < 4; q++) {
            float zx, zy; up2(zz[q], zx, zy);
            float v = (zx + zy + sb[lane]) * swp[lane];
#pragma unroll
            for (int o = 16; o > 0; o >>= 1) v += __shfl_xor_sync(0xffffffffu, v, o);
            if (lane == 0) out[g0 + q] = 1.f / (1.f + expf(-(v + bp)));
        }
    }
}

// ---------------------------------------------------------------------------
extern "C" void kernel_launch(void* const* d_in, const int* in_sizes, int n_in,
                              void* d_out, int out_size)
{
    const float* feature = (const float*)d_in[0];
    const int*   edges   = (const int*)d_in[1];
    const float* W1   = (const float*)d_in[2];
    const float* a_s1 = (const float*)d_in[3];
    const float* a_d1 = (const float*)d_in[4];
    const float* b1   = (const float*)d_in[5];
    const float* W2   = (const float*)d_in[6];
    const float* a_s2 = (const float*)d_in[7];
    const float* a_d2 = (const float*)d_in[8];
    const float* b2   = (const float*)d_in[9];
    const float* Wlin = (const float*)d_in[10];
    const float* blin = (const float*)d_in[11];
    const float* Wprd = (const float*)d_in[12];
    const float* bprd = (const float*)d_in[13];
    float* out = (float*)d_out;

    int sms = 148;
    cudaDeviceGetAttribute(&sms, cudaDevAttrMultiProcessorCount, 0);

    cudaFuncSetAttribute(gat_fused_kernel,
                         cudaFuncAttributeMaxDynamicSharedMemorySize, SMEM_A_BYTES);
    cudaFuncSetAttribute(gat_mlp_kernel,
                         cudaFuncAttributeMaxDynamicSharedMemorySize, MLP_SMEM_BYTES);

    gat_fused_kernel<<<sms, 512, SMEM_A_BYTES>>>(feature, edges, W1, a_s1, a_d1, b1,
                                                 W2, a_s2, a_d2, b2);
    gat_mlp_kernel<<<sms, 1024, MLP_SMEM_BYTES>>>(Wlin, blin, Wprd, bprd, out);
}

// round 12
// speedup vs baseline: 1.7164x; 1.0054x over previous
#include <cuda_runtime.h>

#define BG   16384
#define NN   14
#define FIN  128
#define HH   4
#define CC   64
#define HC   256       // H*C
#define EE   182
#define ET   196       // EE + NN self loops
#define LIN  896       // N*C
#define LOUT 32
#define XP   20        // transposed-x pitch (floats)

// global scratch for h2 between kernels
__device__ __align__(16) float g_h2[(size_t)BG * LIN];

typedef unsigned long long u64;

// ---- packed f32x2 helpers (Blackwell FFMA2/FADD2 path) ----
__device__ __forceinline__ u64 pk2(float a, float b) {
    u64 r; asm("mov.b64 %0,{%1,%2};" : "=l"(r) : "f"(a), "f"(b)); return r;
}
__device__ __forceinline__ void up2(u64 v, float& a, float& b) {
    asm("mov.b64 {%0,%1},%2;" : "=f"(a), "=f"(b) : "l"(v));
}
__device__ __forceinline__ void fma2(u64& d, u64 a, u64 b) {
    asm("fma.rn.f32x2 %0,%1,%2,%0;" : "+l"(d) : "l"(a), "l"(b));
}
__device__ __forceinline__ void add2(u64& d, u64 a) {
    asm("add.rn.f32x2 %0,%0,%1;" : "+l"(d) : "l"(a));
}

// ---- kernel A smem layout (float offsets) ----
// [0,32768)      W1 (128 x 256)
// [32768,49152)  W2 (64 x 256)
// [49152,50176)  wa1 [128][8]
// [50176,50688)  wa2 [64][8]
// per group: base = 50688 + gid*GBLK  (GBLK multiple of 4 -> 16B alignment)
//   +0     region R (2688): xT [128][20]=2560 | shh [3][896]=2688 | x2T [64][20]=1280
//   +2688  sAl 112   [n][h][s,d]
//   +2800  sA  784   [h][d][s]
//   +3584  edges: 196 u16 (98 floats) + 2 pad
#define GBLK      3684
#define OFF_AL    2688
#define OFF_AMAT  2800
#define OFF_EDGE  3584
#define OFF_WA1   49152
#define OFF_WA2   50176
#define GRP_BASE  50688
#define SMEM_A_FLOATS (GRP_BASE + 2 * GBLK + 4)
#define SMEM_A_BYTES  (SMEM_A_FLOATS * 4)   // 232240 <= 232448

__device__ __forceinline__ void barg(int bid) {         // 256-thread group bar
    asm volatile("bar.sync %0, 256;" :: "r"(bid));
}
__device__ __forceinline__ void barp(int bid) {         // 64-thread pair bar
    asm volatile("bar.sync %0, 64;" :: "r"(bid));
}

// GEMM: accp[i] = (h[2i][col], h[2i+1][col]); x transposed [k][n] pitch XP
template <int K>
__device__ __forceinline__ void gemm14(const float* __restrict__ sW,
                                       const float* __restrict__ sxT,
                                       int col, u64* __restrict__ accp)
{
#pragma unroll
    for (int i = 0; i < 7; i++) accp[i] = 0ull;
#pragma unroll 4
    for (int k = 0; k < K; k++) {
        float w = sW[k * HC + col];
        u64 w2 = pk2(w, w);
        const u64* xp = (const u64*)(sxT + k * XP);
        ulonglong2 q01 = *(const ulonglong2*)(xp);
        ulonglong2 q23 = *(const ulonglong2*)(xp + 2);
        ulonglong2 q45 = *(const ulonglong2*)(xp + 4);
        u64 x6 = xp[6];
        fma2(accp[0], q01.x, w2); fma2(accp[1], q01.y, w2);
        fma2(accp[2], q23.x, w2); fma2(accp[3], q23.y, w2);
        fma2(accp[4], q45.x, w2); fma2(accp[5], q45.y, w2);
        fma2(accp[6], x6, w2);
    }
}

// pair-local logits: the 28 outputs of head h (sAl[n*8 + 2h + sd]) computed by
// 56 of the 64 pair threads as k-split half dots + shfl combine.
template <int K>
__device__ __forceinline__ void logits_pair(const float* __restrict__ sxT,
                                            const float* __restrict__ wa,
                                            float* __restrict__ sAl,
                                            int ptid, int h)
{
    int o = ptid >> 1;
    int khalf = ptid & 1;
    int oc = (o < 28) ? o : 27;
    int n = oc >> 1, sd = oc & 1, hs = 2 * h + sd;
    const float* xp = sxT + khalf * (K / 2) * XP + n;
    const float* wp = wa + khalf * (K / 2) * 8 + hs;
    float acc = 0.f;
#pragma unroll 4
    for (int k = 0; k < K / 2; k++)
        acc = fmaf(xp[k * XP], wp[k * 8], acc);
    acc += __shfl_xor_sync(0xffffffffu, acc, 1);
    if (khalf == 0 && o < 28) sAl[n * 8 + hs] = acc;
}

// pair-local edge pass: exp(leakyrelu) into own head's dense A slice
__device__ __forceinline__ void edge_pair(const float* __restrict__ sAl,
                                          float* __restrict__ sA,
                                          const unsigned short* __restrict__ sEdge,
                                          int ptid, int h)
{
    for (int e = ptid; e < ET; e += 64) {
        int v = sEdge[e];
        int s_ = v & 255, d_ = (v >> 8) & 255;
        float ev = sAl[s_ * 8 + 2 * h] + sAl[d_ * 8 + 2 * h + 1];
        ev = (ev > 0.f) ? ev : 0.2f * ev;
        atomicAdd(&sA[(h * NN + d_) * NN + s_], __expf(ev));
    }
}

// aggregation (softmax folded): aggf[n] = (sum_s A[h][n][s]*h[s][col]) / rowsum;
// heads 1..3 publish to shh, head 0 keeps registers.
__device__ __forceinline__ void agg_heads(const float* __restrict__ sA,
                                          const u64* __restrict__ accp,
                                          float* __restrict__ shh,
                                          float* __restrict__ aggf,
                                          int hh, int cch)
{
#pragma unroll
    for (int n = 0; n < NN; n++) {
        const u64* Ar = (const u64*)(sA + (hh * NN + n) * NN);
        u64 t = 0ull, dn = 0ull;
#pragma unroll
        for (int i = 0; i < 7; i++) { u64 a = Ar[i]; fma2(t, a, accp[i]); add2(dn, a); }
        float tx, ty, dx, dy;
        up2(t, tx, ty); up2(dn, dx, dy);
        aggf[n] = __fdividef(tx + ty, dx + dy);
    }
    if (hh > 0) {
        float* dst = shh + (hh - 1) * LIN + cch;
#pragma unroll
        for (int n = 0; n < NN; n++) dst[n * 64] = aggf[n];
    }
}

// head-0 fold: aggf[n] = 0.25*(aggf[n] + 3 slots) + bias
__device__ __forceinline__ void fold_heads(const float* __restrict__ shh,
                                           float* __restrict__ aggf,
                                           float bc, int cch)
{
#pragma unroll
    for (int n = 0; n < NN; n++) {
        float s = aggf[n] + shh[n * 64 + cch] + shh[LIN + n * 64 + cch]
                + shh[2 * LIN + n * 64 + cch];
        aggf[n] = 0.25f * s + bc;
    }
}

// ---------------------------------------------------------------------------
__global__ __launch_bounds__(512, 1)
void gat_fused_kernel(const float* __restrict__ feature,
                      const int* __restrict__ edge_raw,   // int32 OR int64 (detected)
                      const float* __restrict__ W1, const float* __restrict__ a_s1,
                      const float* __restrict__ a_d1, const float* __restrict__ b1,
                      const float* __restrict__ W2, const float* __restrict__ a_s2,
                      const float* __restrict__ a_d2, const float* __restrict__ b2)
{
    extern __shared__ float sm[];
    float* sW1 = sm;
    float* sW2 = sm + 32768;
    float* wa1 = sm + OFF_WA1;
    float* wa2 = sm + OFF_WA2;

    const int tid  = threadIdx.x;
    const int gid  = tid >> 8;
    const int gtid = tid & 255;
    const int hp   = gtid >> 6;        // head / warp-pair id (0..3)
    const int ptid = gtid & 63;        // index within pair
    const int cch  = gtid & 63;        // channel within head (== ptid)
    const int bid  = gid + 1;          // group bar id (1,2)
    const int pbid = 4 + gid * 4 + hp; // pair bar id (4..11)

    float* gb    = sm + GRP_BASE + gid * GBLK;
    float* xT    = gb;                 // [128][XP]
    float* shh   = gb;                 // [3][896] overlays xT after it dies
    float* x2T   = gb;                 // [64][XP] overlays (fenced by barriers)
    float* sAl   = gb + OFF_AL;
    float* sA    = gb + OFF_AMAT;
    unsigned short* sEdge = (unsigned short*)(gb + OFF_EDGE);
    int*   sFlag = (int*)(sm + GRP_BASE + 2 * GBLK);

    if (tid == 0) {
        int allz = 1;
        for (int i = 0; i < 64; i++) allz &= (edge_raw[2 * i + 1] == 0);
        *sFlag = allz;
    }
    // preload weights (shared by both groups)
    {
        const float4* w1v = (const float4*)W1;
        float4* d1 = (float4*)sW1;
        for (int i = tid; i < FIN * HC / 4; i += 512) d1[i] = w1v[i];
        const float4* w2v = (const float4*)W2;
        float4* d2 = (float4*)sW2;
        for (int i = tid; i < CC * HC / 4; i += 512) d2[i] = w2v[i];
    }
    __syncthreads();

    // precompute wa1[k][h*2+sd] = sum_c W1[k][h*64+c]*a_{s,d}1[h*64+c]
    for (int j = 0; j < 2; j++) {
        int idx = tid * 2 + j;               // 0..1023
        int k = idx >> 3, hs = idx & 7, h = hs >> 1;
        const float* av = (hs & 1) ? a_d1 : a_s1;
        const float* wr = sW1 + k * HC + h * CC;
        const float* ar = av + h * CC;
        float acc = 0.f;
#pragma unroll 8
        for (int c = 0; c < CC; c++) acc = fmaf(wr[c], ar[c], acc);
        wa1[idx] = acc;
    }
    {   // wa2: 512 entries
        int idx = tid;
        int k = idx >> 3, hs = idx & 7, h = hs >> 1;
        const float* av = (hs & 1) ? a_d2 : a_s2;
        const float* wr = sW2 + k * HC + h * CC;
        const float* ar = av + h * CC;
        float acc = 0.f;
#pragma unroll 8
        for (int c = 0; c < CC; c++) acc = fmaf(wr[c], ar[c], acc);
        wa2[idx] = acc;
    }
    const float b1c = b1[cch], b2c = b2[cch];
    __syncthreads();
    const int is64 = *sFlag;

    for (int g = blockIdx.x * 2 + gid; g < BG; g += gridDim.x * 2) {
        // ---- load xT + edges, zero all of A ----
        if (gtid < FIN) {
            const float* fp = feature + (size_t)g * (NN * FIN) + gtid;
#pragma unroll
            for (int n = 0; n < NN; n++) xT[gtid * XP + n] = fp[n * FIN];
        }
        if (gtid < EE) {
            int s, d;
            if (is64) {
                const long long* ep = (const long long*)edge_raw + ((size_t)g * EE + gtid) * 2;
                s = (int)ep[0]; d = (int)ep[1];
            } else {
                const int* ep = edge_raw + ((size_t)g * EE + gtid) * 2;
                s = ep[0]; d = ep[1];
            }
            sEdge[gtid] = (unsigned short)(s | (d << 8));
        } else if (gtid < ET) {
            int v = gtid - EE;
            sEdge[gtid] = (unsigned short)(v | (v << 8));
        }
        for (int i = gtid; i < HH * NN * NN; i += 256) sA[i] = 0.f;
        barg(bid);                                        // BAR1: inputs ready

        // ---- layer 1 ----
        u64 accp[7];
        float aggf[NN];
        gemm14<FIN>(sW1, xT, gtid, accp);
        logits_pair<FIN>(xT, wa1, sAl, ptid, hp);
        barp(pbid);                                       // pair: sAl slice ready

        edge_pair(sAl, sA, sEdge, ptid, hp);
        barp(pbid);                                       // pair: sA slice ready

        agg_heads(sA, accp, shh, aggf, hp, cch);
        barg(bid);                                        // BAR-PF: all shh written

        if (gtid < 64) {                                  // pair 0 folds + writes x2T
            fold_heads(shh, aggf, b1c, cch);
            barp(4 + gid * 4);                            // fold reads done in pair 0
#pragma unroll
            for (int n = 0; n < NN; n++) x2T[cch * XP + n] = fmaxf(aggf[n], 0.f);
        }
        // zero own sA slice for layer 2 (readers finished before BAR-PF)
        for (int i = ptid; i < NN * NN; i += 64) sA[hp * NN * NN + i] = 0.f;
        barg(bid);                                        // BAR-F: x2T + zeros ready

        // ---- layer 2 ----
        gemm14<CC>(sW2, x2T, gtid, accp);
        logits_pair<CC>(x2T, wa2, sAl, ptid, hp);
        barp(pbid);                                       // pair: sAl slice ready

        edge_pair(sAl, sA, sEdge, ptid, hp);
        barp(pbid);                                       // pair: sA slice ready

        agg_heads(sA, accp, shh, aggf, hp, cch);
        barg(bid);                                        // BAR-PF2: all shh written

        if (gtid < 64) {
            fold_heads(shh, aggf, b2c, cch);
            float* orow = g_h2 + (size_t)g * LIN;
#pragma unroll
            for (int n = 0; n < NN; n++) orow[n * 64 + cch] = aggf[n];
        }
        barg(bid);                                        // BAR-END: protect region R
    }
}

// ---------------------------------------------------------------------------
// kernel B: z = h2 @ W_lin + b_lin ; p = z @ W_pred + b_pred ; out = sigmoid(p)
// 1024 threads; each warp processes 4 graphs per pass (W_lin smem reuse x4);
// h rows read straight from gmem as broadcast LDG.128.
// ---------------------------------------------------------------------------
#define WLT_PITCH 900
#define MLP_SMEM_FLOATS (LOUT * WLT_PITCH + 64)
#define MLP_SMEM_BYTES  (MLP_SMEM_FLOATS * 4)   // 115,456 B

__global__ __launch_bounds__(1024, 1)
void gat_mlp_kernel(const float* __restrict__ Wlin, const float* __restrict__ blin,
                    const float* __restrict__ Wpred, const float* __restrict__ bpred,
                    float* __restrict__ out)
{
    extern __shared__ float sm[];
    float* sWt = sm;                            // [32][900]
    float* sb  = sm + LOUT * WLT_PITCH;         // [32]
    float* swp = sb + LOUT;                     // [32]

    const int tid = threadIdx.x;
    const int lane = tid & 31;
    const int w = tid >> 5;

    for (int i = tid; i < LIN * LOUT; i += 1024) {
        int r = i >> 5, c = i & 31;             // Wlin[r][c]
        sWt[c * WLT_PITCH + r] = Wlin[i];
    }
    if (tid < LOUT) { sb[tid] = blin[tid]; swp[tid] = Wpred[tid]; }
    __syncthreads();
    const float bp = bpred[0];

    const float* wr = sWt + lane * WLT_PITCH;
    for (int g0 = (blockIdx.x * 32 + w) * 4; g0 < BG; g0 += gridDim.x * 32 * 4) {
        const float* h0 = g_h2 + (size_t)g0 * LIN;
        const float* h1 = h0 + LIN;
        const float* h2 = h0 + 2 * LIN;
        const float* h3 = h0 + 3 * LIN;
        u64 z0 = 0ull, z1 = 0ull, z2 = 0ull, z3 = 0ull;
#pragma unroll 4
        for (int i = 0; i < LIN; i += 4) {
            ulonglong2 wq = *(const ulonglong2*)(wr + i);
            ulonglong2 a0 = *(const ulonglong2*)(h0 + i);
            ulonglong2 a1 = *(const ulonglong2*)(h1 + i);
            ulonglong2 a2 = *(const ulonglong2*)(h2 + i);
            ulonglong2 a3 = *(const ulonglong2*)(h3 + i);
            fma2(z0, wq.x, a0.x); fma2(z0, wq.y, a0.y);
            fma2(z1, wq.x, a1.x); fma2(z1, wq.y, a1.y);
            fma2(z2, wq.x, a2.x); fma2(z2, wq.y, a2.y);
            fma2(z3, wq.x, a3.x); fma2(z3, wq.y, a3.y);
        }
        u64 zz[4] = {z0, z1, z2, z3};
#pragma unroll
        for (int q = 0; q < 4; q++) {
            float zx, zy; up2(zz[q], zx, zy);
            float v = (zx + zy + sb[lane]) * swp[lane];
#pragma unroll
            for (int o = 16; o > 0; o >>= 1) v += __shfl_xor_sync(0xffffffffu, v, o);
            if (lane == 0) out[g0 + q] = 1.f / (1.f + expf(-(v + bp)));
        }
    }
}

// ---------------------------------------------------------------------------
extern "C" void kernel_launch(void* const* d_in, const int* in_sizes, int n_in,
                              void* d_out, int out_size)
{
    const float* feature = (const float*)d_in[0];
    const int*   edges   = (const int*)d_in[1];
    const float* W1   = (const float*)d_in[2];
    const float* a_s1 = (const float*)d_in[3];
    const float* a_d1 = (const float*)d_in[4];
    const float* b1   = (const float*)d_in[5];
    const float* W2   = (const float*)d_in[6];
    const float* a_s2 = (const float*)d_in[7];
    const float* a_d2 = (const float*)d_in[8];
    const float* b2   = (const float*)d_in[9];
    const float* Wlin = (const float*)d_in[10];
    const float* blin = (const float*)d_in[11];
    const float* Wprd = (const float*)d_in[12];
    const float* bprd = (const float*)d_in[13];
    float* out = (float*)d_out;

    int sms = 148;
    cudaDeviceGetAttribute(&sms, cudaDevAttrMultiProcessorCount, 0);

    cudaFuncSetAttribute(gat_fused_kernel,
                         cudaFuncAttributeMaxDynamicSharedMemorySize, SMEM_A_BYTES);
    cudaFuncSetAttribute(gat_mlp_kernel,
                         cudaFuncAttributeMaxDynamicSharedMemorySize, MLP_SMEM_BYTES);

    gat_fused_kernel<<<sms, 512, SMEM_A_BYTES>>>(feature, edges, W1, a_s1, a_d1, b1,
                                                 W2, a_s2, a_d2, b2);
    gat_mlp_kernel<<<sms, 1024, MLP_SMEM_BYTES>>>(Wlin, blin, Wprd, bprd, out);
}